// round 13
// baseline (speedup 1.0000x reference)
#include <cuda_runtime.h>

#define HH 512
#define WW 512
#define NCHUNK 32
#define RPC (HH / NCHUNK)   // 16 rows per block -> grid 2048

__device__ __forceinline__ int rrow(int r) {
    return r < 0 ? -r : (r >= HH ? 2 * HH - 2 - r : r);
}

__device__ __forceinline__ float med3(float a, float b, float c) {
    return fmaxf(fminf(a, b), fminf(fmaxf(a, b), c));
}

// insert a into sorted pair (p <= q) -> sorted triple (4 ops)
__device__ __forceinline__ void ins3(float a, float p, float q,
                                     float& lo, float& mi, float& hi) {
    lo = fminf(a, p);
    hi = fmaxf(a, q);
    mi = fmaxf(p, fminf(a, q));
}

// one output row from 6 locally-computed sorted column triples (L,0,1,2,3,R)
__device__ __forceinline__ void emit_row(
    const float tlL, const float tmL, const float thL,
    const float tl0, const float tm0, const float th0,
    const float tl1, const float tm1, const float th1,
    const float tl2, const float tm2, const float th2,
    const float tl3, const float tm3, const float th3,
    const float tlR, const float tmR, const float thR,
    float* __restrict__ orow) {

    // lows: max3, pair-shared
    float ul01 = fmaxf(tl0, tl1);
    float ul23 = fmaxf(tl2, tl3);
    float Ax = fmaxf(ul01, tlL);
    float Ay = fmaxf(ul01, tl2);
    float Az = fmaxf(ul23, tl1);
    float Aw = fmaxf(ul23, tlR);
    // highs: min3, pair-shared
    float vh01 = fminf(th0, th1);
    float vh23 = fminf(th2, th3);
    float Cx = fminf(vh01, thL);
    float Cy = fminf(vh01, th2);
    float Cz = fminf(vh23, th1);
    float Cw = fminf(vh23, thR);
    // mids: med3, pair-shared
    float mn01 = fminf(tm0, tm1), mx01 = fmaxf(tm0, tm1);
    float mn23 = fminf(tm2, tm3), mx23 = fmaxf(tm2, tm3);
    float Bx = fmaxf(mn01, fminf(mx01, tmL));
    float By = fmaxf(mn01, fminf(mx01, tm2));
    float Bz = fmaxf(mn23, fminf(mx23, tm1));
    float Bw = fmaxf(mn23, fminf(mx23, tmR));

    float4 o;
    o.x = med3(Ax, Bx, Cx);
    o.y = med3(Ay, By, Cy);
    o.z = med3(Az, Bz, Cz);
    o.w = med3(Aw, Bw, Cw);
    *(float4*)orow = o;
}

// One double-row step, 3-row window, shuffle-free (local halo columns).
template<bool INTERIOR>
__device__ __forceinline__ void step2(
    const float* __restrict__ base,
    const float* __restrict__ prow, const float* __restrict__ plrow,
    const float* __restrict__ prrow, float* __restrict__ orow,
    const int y0, const int k, const int c0, const int xl, const int xr,
    float4& a4, float4& b4, float4& c4,
    float& al, float& bl, float& cl,
    float& ar, float& br, float& cr) {

    float4 d4, n4;
    float dl, nl, dr, nr;
    if (INTERIOR) {
        d4 = __ldg((const float4*)(prow + (k + 2) * WW));
        n4 = __ldg((const float4*)(prow + (k + 3) * WW));
        dl = __ldg(plrow + (k + 2) * WW);
        nl = __ldg(plrow + (k + 3) * WW);
        dr = __ldg(prrow + (k + 2) * WW);
        nr = __ldg(prrow + (k + 3) * WW);
    } else {
        const int y2 = rrow(y0 + k + 2);
        const int y3 = rrow(y0 + k + 3);
        d4 = __ldg((const float4*)(base + (size_t)y2 * WW + c0));
        n4 = __ldg((const float4*)(base + (size_t)y3 * WW + c0));
        dl = __ldg(base + (size_t)y2 * WW + xl);
        nl = __ldg(base + (size_t)y3 * WW + xl);
        dr = __ldg(base + (size_t)y2 * WW + xr);
        nr = __ldg(base + (size_t)y3 * WW + xr);
    }

    // Sorted pairs of the two shared rows (b,c), per column (6 cols)
    float p0 = fminf(b4.x, c4.x), q0 = fmaxf(b4.x, c4.x);
    float p1 = fminf(b4.y, c4.y), q1 = fmaxf(b4.y, c4.y);
    float p2 = fminf(b4.z, c4.z), q2 = fmaxf(b4.z, c4.z);
    float p3 = fminf(b4.w, c4.w), q3 = fmaxf(b4.w, c4.w);
    float pl = fminf(bl, cl),     ql = fmaxf(bl, cl);
    float pr = fminf(br, cr),     qr = fmaxf(br, cr);

    // ---- output row y0+k: insert rows above (a*) ----
    {
        float lL,mL,hL,l0,m0,h0,l1,m1,h1,l2,m2,h2,l3,m3,h3,lR,mR,hR;
        ins3(al,   pl, ql, lL, mL, hL);
        ins3(a4.x, p0, q0, l0, m0, h0);
        ins3(a4.y, p1, q1, l1, m1, h1);
        ins3(a4.z, p2, q2, l2, m2, h2);
        ins3(a4.w, p3, q3, l3, m3, h3);
        ins3(ar,   pr, qr, lR, mR, hR);
        emit_row(lL,mL,hL, l0,m0,h0, l1,m1,h1, l2,m2,h2, l3,m3,h3, lR,mR,hR,
                 orow + k * WW);
    }

    // ---- output row y0+k+1: insert rows below (d*) ----
    {
        float lL,mL,hL,l0,m0,h0,l1,m1,h1,l2,m2,h2,l3,m3,h3,lR,mR,hR;
        ins3(dl,   pl, ql, lL, mL, hL);
        ins3(d4.x, p0, q0, l0, m0, h0);
        ins3(d4.y, p1, q1, l1, m1, h1);
        ins3(d4.z, p2, q2, l2, m2, h2);
        ins3(d4.w, p3, q3, l3, m3, h3);
        ins3(dr,   pr, qr, lR, mR, hR);
        emit_row(lL,mL,hL, l0,m0,h0, l1,m1,h1, l2,m2,h2, l3,m3,h3, lR,mR,hR,
                 orow + (k + 1) * WW);
    }

    // slide window down by 2 (renamed away under full unroll)
    a4 = c4; b4 = d4; c4 = n4;
    al = cl; bl = dl; cl = nl;
    ar = cr; br = dr; cr = nr;
}

template<bool INTERIOR>
__device__ __forceinline__ void median_chunk(
    const float* __restrict__ base, float* __restrict__ obase,
    const int lane, const int stripe, const int y0) {

    const int c0 = stripe * 128 + lane * 4;
    // column-reflected halo indices (only image-edge lanes differ)
    const int xl = (c0 == 0)        ? 1   : c0 - 1;
    const int xr = (c0 + 4 == WW)   ? 510 : c0 + 4;

    const float* __restrict__ prow  = base  + (size_t)y0 * WW + c0;
    const float* __restrict__ plrow = base  + (size_t)y0 * WW + xl;
    const float* __restrict__ prrow = base  + (size_t)y0 * WW + xr;
    float* __restrict__       orow  = obase + (size_t)y0 * WW + c0;

    float4 a4, b4, c4;
    float al, bl, cl, ar, br, cr;
    if (INTERIOR) {
        a4 = __ldg((const float4*)(prow - WW));
        b4 = __ldg((const float4*)(prow));
        c4 = __ldg((const float4*)(prow + WW));
        al = __ldg(plrow - WW);  bl = __ldg(plrow);  cl = __ldg(plrow + WW);
        ar = __ldg(prrow - WW);  br = __ldg(prrow);  cr = __ldg(prrow + WW);
    } else {
        const int ym = rrow(y0 - 1);
        const int yp = rrow(y0 + 1);
        a4 = __ldg((const float4*)(base + (size_t)ym * WW + c0));
        b4 = __ldg((const float4*)(base + (size_t)y0 * WW + c0));
        c4 = __ldg((const float4*)(base + (size_t)yp * WW + c0));
        al = __ldg(base + (size_t)ym * WW + xl);
        bl = __ldg(base + (size_t)y0 * WW + xl);
        cl = __ldg(base + (size_t)yp * WW + xl);
        ar = __ldg(base + (size_t)ym * WW + xr);
        br = __ldg(base + (size_t)y0 * WW + xr);
        cr = __ldg(base + (size_t)yp * WW + xr);
    }

    if (INTERIOR) {
#pragma unroll 8
        for (int k = 0; k < RPC; k += 2)
            step2<true>(base, prow, plrow, prrow, orow, y0, k, c0, xl, xr,
                        a4, b4, c4, al, bl, cl, ar, br, cr);
    } else {
#pragma unroll 2
        for (int k = 0; k < RPC; k += 2)
            step2<false>(base, prow, plrow, prrow, orow, y0, k, c0, xl, xr,
                         a4, b4, c4, al, bl, cl, ar, br, cr);
    }
}

__global__ __launch_bounds__(128, 8)
void median3x3_kernel(const float* __restrict__ x, float* __restrict__ out) {
    const int lane   = threadIdx.x & 31;
    const int stripe = threadIdx.x >> 5;
    const int img    = blockIdx.y;
    const int chunk  = blockIdx.x;

    const float* __restrict__ base  = x   + (size_t)img * HH * WW;
    float* __restrict__       obase = out + (size_t)img * HH * WW;
    const int y0 = chunk * RPC;

    if (chunk > 0 && chunk < NCHUNK - 1) {
        median_chunk<true>(base, obase, lane, stripe, y0);
    } else {
        median_chunk<false>(base, obase, lane, stripe, y0);
    }
}

extern "C" void kernel_launch(void* const* d_in, const int* in_sizes, int n_in,
                              void* d_out, int out_size) {
    const float* x = (const float*)d_in[0];
    float* out = (float*)d_out;
    const int nimg = in_sizes[0] / (HH * WW);   // 64 for [8,8,512,512]
    dim3 grid(NCHUNK, nimg);
    median3x3_kernel<<<grid, 128>>>(x, out);
}